// round 5
// baseline (speedup 1.0000x reference)
#include <cuda_runtime.h>
#include <cuda_fp16.h>
#include <math.h>

// Problem constants (fixed shapes)
#define NN 100000
#define NE 1600000
#define NG 512
#define FIN 128
#define HH 64
#define HS 192   // 3*H concat width
#define GF 576   // 3*HS graph feature width

#define SCAN_CH 1024
#define NSB ((NN + SCAN_CH - 1) / SCAN_CH)   // 98 scan blocks

// ---------------- scratch (static device globals; no runtime alloc) -------
__device__ __align__(16) float  g_agg[(size_t)NN * FIN];   // 51.2 MB
__device__ __align__(16) float  g_hs[(size_t)NN * HS];     // 76.8 MB
__device__ __align__(16) __half g_x16[(size_t)NN * FIN];   // 25.6 MB: fp16 copy of x
__device__ __align__(16) __half g_h16[(size_t)NN * FIN];   // 25.6 MB: L0|L1 outputs fp16
__device__ __align__(16) int g_rowptr[NN + 4];
__device__ __align__(16) int g_cursor[NN + 4];   // degree accumulator, then fill cursor
__device__ int g_csr[NE];
__device__ int g_bsum[NSB];
__device__ int g_boff[NSB + 1];
__device__ int g_cnt[NG];
__device__ int g_off[NG + 1];
__device__ int g_is64;

// ---------------- index dtype handling -------------------------------------
__device__ __forceinline__ long ld_idx(const void* p, long i) {
    if (g_is64) return (long)((const long long*)p)[i];
    return (long)((const int*)p)[i];
}

__global__ void k_detect(const void* edge) {
    // int64 indices < 2^31 => every odd 32-bit word is zero. Warp-parallel probe.
    const int* p = (const int*)edge;
    int t = threadIdx.x;
    int nz = (p[2 * t + 1] != 0) ? 1 : 0;
    unsigned m = __ballot_sync(0xffffffffu, nz);
    if (t == 0) g_is64 = (m == 0) ? 1 : 0;
}

// ---------------- fp16 conversion of x -------------------------------------
__global__ void k_cvt_x(const float* __restrict__ x) {
    long i = ((long)blockIdx.x * 256 + threadIdx.x) * 4;
    if (i < (long)NN * FIN) {
        float4 v = *(const float4*)&x[i];
        __half2 h0 = __floats2half2_rn(v.x, v.y);
        __half2 h1 = __floats2half2_rn(v.z, v.w);
        *(__half2*)&g_x16[i]     = h0;
        *(__half2*)&g_x16[i + 2] = h1;
    }
}

// ---------------- CSR build (once per launch; reused by all 3 layers) ------
__global__ void k_zero_deg() {
    int i = blockIdx.x * 256 + threadIdx.x;
    if (i < NN) g_cursor[i] = 0;
}

__global__ void k_deg(const void* __restrict__ edge) {
    long e = (long)blockIdx.x * 256 + threadIdx.x;
    if (e < NE) {
        int d = (int)ld_idx(edge, (long)NE + e);
        atomicAdd(&g_cursor[d], 1);
    }
}

// Pass 1: per-block sums of 1024 degrees (256 threads x int4).
__global__ void __launch_bounds__(256) k_bsum() {
    __shared__ int ws[8];
    const int b = blockIdx.x, t = threadIdx.x;
    const int base = b * SCAN_CH + t * 4;
    int s = 0;
    if (base < NN) {
        int4 v = *(const int4*)&g_cursor[base];
        s = (v.x + v.y) + (v.z + v.w);
    }
#pragma unroll
    for (int o = 16; o > 0; o >>= 1) s += __shfl_down_sync(0xffffffffu, s, o);
    if ((t & 31) == 0) ws[t >> 5] = s;
    __syncthreads();
    if (t < 8) {
        int v = ws[t];
#pragma unroll
        for (int o = 4; o > 0; o >>= 1) v += __shfl_down_sync(0xffu, v, o);
        if (t == 0) g_bsum[b] = v;
    }
}

// Pass 2: scan the 98 block sums in one tiny block.
__global__ void __launch_bounds__(128) k_bscan() {
    __shared__ int s[128];
    int t = threadIdx.x;
    int v = (t < NSB) ? g_bsum[t] : 0;
    s[t] = v;
    __syncthreads();
#pragma unroll
    for (int d = 1; d < 128; d <<= 1) {
        int u = (t >= d) ? s[t - d] : 0;
        __syncthreads();
        s[t] += u;
        __syncthreads();
    }
    g_boff[t] = (t == 0) ? 0 : s[t - 1];
    if (t == NSB - 1) g_rowptr[NN] = s[t];
}

// Pass 3: per-block rescan -> rowptr, and initialize fill cursor in one pass.
__global__ void __launch_bounds__(256) k_rowptr() {
    __shared__ int s[256];
    const int b = blockIdx.x, t = threadIdx.x;
    const int base = b * SCAN_CH + t * 4;
    int d0 = 0, d1 = 0, d2 = 0, d3 = 0;
    if (base < NN) {
        int4 v = *(const int4*)&g_cursor[base];
        d0 = v.x; d1 = v.y; d2 = v.z; d3 = v.w;
    }
    s[t] = d0 + d1 + d2 + d3;
    __syncthreads();
#pragma unroll
    for (int d = 1; d < 256; d <<= 1) {
        int u = (t >= d) ? s[t - d] : 0;
        __syncthreads();
        s[t] += u;
        __syncthreads();
    }
    int off = g_boff[b] + ((t == 0) ? 0 : s[t - 1]);
    if (base < NN) {
        int4 r;
        r.x = off;
        r.y = off + d0;
        r.z = off + d0 + d1;
        r.w = off + d0 + d1 + d2;
        *(int4*)&g_rowptr[base] = r;
        *(int4*)&g_cursor[base] = r;   // cursor init fused
    }
}

__global__ void k_fill(const void* __restrict__ edge) {
    long e = (long)blockIdx.x * 256 + threadIdx.x;
    if (e < NE) {
        int s = (int)ld_idx(edge, e);
        int d = (int)ld_idx(edge, (long)NE + e);
        int pos = atomicAdd(&g_cursor[d], 1);
        g_csr[pos] = s;
    }
}

// ---------------- pull-aggregation over fp16 payloads -----------------------
// One warp per destination node. All fp16 feature matrices have stride 128.
// F=128: 4 halves (8B) per lane; F=64: 2 halves (4B) per lane. fp32 accum.
template <int F>
__global__ void __launch_bounds__(256) k_pull(int use_x, int in_off) {
    const __half* in = use_x ? g_x16 : (g_h16 + in_off);

    int warp = (blockIdx.x * 256 + threadIdx.x) >> 5;
    int lane = threadIdx.x & 31;
    if (warp >= NN) return;
    int beg = g_rowptr[warp], end = g_rowptr[warp + 1];

    if (F == 128) {
        float4 acc = make_float4(0.f, 0.f, 0.f, 0.f);
        for (int j = beg; j < end; j += 32) {
            int n = min(32, end - j);
            int idx = (lane < n) ? g_csr[j + lane] : 0;
            int t = 0;
            for (; t + 4 <= n; t += 4) {
                int u0 = __shfl_sync(0xffffffffu, idx, t + 0);
                int u1 = __shfl_sync(0xffffffffu, idx, t + 1);
                int u2 = __shfl_sync(0xffffffffu, idx, t + 2);
                int u3 = __shfl_sync(0xffffffffu, idx, t + 3);
                uint2 r0 = *(const uint2*)&in[(long)u0 * 128 + lane * 4];
                uint2 r1 = *(const uint2*)&in[(long)u1 * 128 + lane * 4];
                uint2 r2 = *(const uint2*)&in[(long)u2 * 128 + lane * 4];
                uint2 r3 = *(const uint2*)&in[(long)u3 * 128 + lane * 4];
                float2 a0 = __half22float2(*(__half2*)&r0.x);
                float2 b0 = __half22float2(*(__half2*)&r0.y);
                float2 a1 = __half22float2(*(__half2*)&r1.x);
                float2 b1 = __half22float2(*(__half2*)&r1.y);
                float2 a2 = __half22float2(*(__half2*)&r2.x);
                float2 b2 = __half22float2(*(__half2*)&r2.y);
                float2 a3 = __half22float2(*(__half2*)&r3.x);
                float2 b3 = __half22float2(*(__half2*)&r3.y);
                acc.x += (a0.x + a1.x) + (a2.x + a3.x);
                acc.y += (a0.y + a1.y) + (a2.y + a3.y);
                acc.z += (b0.x + b1.x) + (b2.x + b3.x);
                acc.w += (b0.y + b1.y) + (b2.y + b3.y);
            }
            for (; t < n; t++) {
                int u = __shfl_sync(0xffffffffu, idx, t);
                uint2 r = *(const uint2*)&in[(long)u * 128 + lane * 4];
                float2 a = __half22float2(*(__half2*)&r.x);
                float2 b = __half22float2(*(__half2*)&r.y);
                acc.x += a.x; acc.y += a.y; acc.z += b.x; acc.w += b.y;
            }
        }
        *(float4*)&g_agg[(long)warp * F + lane * 4] = acc;
    } else {
        float2 acc = make_float2(0.f, 0.f);
        for (int j = beg; j < end; j += 32) {
            int n = min(32, end - j);
            int idx = (lane < n) ? g_csr[j + lane] : 0;
            int t = 0;
            for (; t + 4 <= n; t += 4) {
                int u0 = __shfl_sync(0xffffffffu, idx, t + 0);
                int u1 = __shfl_sync(0xffffffffu, idx, t + 1);
                int u2 = __shfl_sync(0xffffffffu, idx, t + 2);
                int u3 = __shfl_sync(0xffffffffu, idx, t + 3);
                float2 a0 = __half22float2(*(const __half2*)&in[(long)u0 * 128 + lane * 2]);
                float2 a1 = __half22float2(*(const __half2*)&in[(long)u1 * 128 + lane * 2]);
                float2 a2 = __half22float2(*(const __half2*)&in[(long)u2 * 128 + lane * 2]);
                float2 a3 = __half22float2(*(const __half2*)&in[(long)u3 * 128 + lane * 2]);
                acc.x += (a0.x + a1.x) + (a2.x + a3.x);
                acc.y += (a0.y + a1.y) + (a2.y + a3.y);
            }
            for (; t < n; t++) {
                int u = __shfl_sync(0xffffffffu, idx, t);
                float2 a = __half22float2(*(const __half2*)&in[(long)u * 128 + lane * 2]);
                acc.x += a.x; acc.y += a.y;
            }
        }
        *(float2*)&g_agg[(long)warp * F + lane * 2] = acc;
    }
}

// ---------------- fused GIN MLP: h = relu(relu(((1+eps)x+agg)W1+b1)W2+b2) ---
// Self-term reads fp32 x / g_hs (full precision). Epilogue writes fp32 g_hs
// (for readout) and, for layers 0/1, an fp16 copy for the next pull.
__global__ void __launch_bounds__(256) k_mlp(const float* __restrict__ x,
                                             int use_x, int in_off, int fin,
                                             const float* __restrict__ eps, int layer,
                                             const float* __restrict__ W1,
                                             const float* __restrict__ B1,
                                             const float* __restrict__ W2,
                                             const float* __restrict__ B2,
                                             int out_off) {
    __shared__ float sA[64][68];
    __shared__ float sB[64][68];

    const int tid = threadIdx.x;
    const int tx = tid & 15;
    const int ty = tid >> 4;
    const int tile = blockIdx.x * 64;

    const float* in = use_x ? x : (g_hs + in_off);
    const int in_stride = use_x ? FIN : HS;
    const float epsv = 1.0f + eps[layer];

    float4 c0 = make_float4(0.f, 0.f, 0.f, 0.f), c1 = c0, c2 = c0, c3 = c0;

    for (int kc = 0; kc < fin; kc += 64) {
#pragma unroll
        for (int s = 0; s < 4; s++) {
            int slot = tid + s * 256;
            int r  = slot >> 4;
            int k4 = slot & 15;
            int rg = tile + r;
            float4 v = make_float4(0.f, 0.f, 0.f, 0.f);
            if (rg < NN) {
                float4 xv = *(const float4*)&in[(long)rg * in_stride + kc + k4 * 4];
                float4 av = *(const float4*)&g_agg[(long)rg * fin + kc + k4 * 4];
                v.x = epsv * xv.x + av.x;
                v.y = epsv * xv.y + av.y;
                v.z = epsv * xv.z + av.z;
                v.w = epsv * xv.w + av.w;
            }
            *(float4*)&sA[r][k4 * 4] = v;
            *(float4*)&sB[r][k4 * 4] = *(const float4*)&W1[(long)(kc + r) * 64 + k4 * 4];
        }
        __syncthreads();
#pragma unroll 8
        for (int k = 0; k < 64; k++) {
            float4 b = *(const float4*)&sB[k][tx * 4];
            float a0 = sA[ty * 4 + 0][k];
            float a1 = sA[ty * 4 + 1][k];
            float a2 = sA[ty * 4 + 2][k];
            float a3 = sA[ty * 4 + 3][k];
            c0.x += a0 * b.x; c0.y += a0 * b.y; c0.z += a0 * b.z; c0.w += a0 * b.w;
            c1.x += a1 * b.x; c1.y += a1 * b.y; c1.z += a1 * b.z; c1.w += a1 * b.w;
            c2.x += a2 * b.x; c2.y += a2 * b.y; c2.z += a2 * b.z; c2.w += a2 * b.w;
            c3.x += a3 * b.x; c3.y += a3 * b.y; c3.z += a3 * b.z; c3.w += a3 * b.w;
        }
        __syncthreads();
    }

    {
        float4 bb = *(const float4*)&B1[tx * 4];
        float4 h;
        h.x = fmaxf(c0.x + bb.x, 0.f); h.y = fmaxf(c0.y + bb.y, 0.f);
        h.z = fmaxf(c0.z + bb.z, 0.f); h.w = fmaxf(c0.w + bb.w, 0.f);
        *(float4*)&sA[ty * 4 + 0][tx * 4] = h;
        h.x = fmaxf(c1.x + bb.x, 0.f); h.y = fmaxf(c1.y + bb.y, 0.f);
        h.z = fmaxf(c1.z + bb.z, 0.f); h.w = fmaxf(c1.w + bb.w, 0.f);
        *(float4*)&sA[ty * 4 + 1][tx * 4] = h;
        h.x = fmaxf(c2.x + bb.x, 0.f); h.y = fmaxf(c2.y + bb.y, 0.f);
        h.z = fmaxf(c2.z + bb.z, 0.f); h.w = fmaxf(c2.w + bb.w, 0.f);
        *(float4*)&sA[ty * 4 + 2][tx * 4] = h;
        h.x = fmaxf(c3.x + bb.x, 0.f); h.y = fmaxf(c3.y + bb.y, 0.f);
        h.z = fmaxf(c3.z + bb.z, 0.f); h.w = fmaxf(c3.w + bb.w, 0.f);
        *(float4*)&sA[ty * 4 + 3][tx * 4] = h;
    }
#pragma unroll
    for (int s = 0; s < 4; s++) {
        int slot = tid + s * 256;
        int r  = slot >> 4;
        int k4 = slot & 15;
        *(float4*)&sB[r][k4 * 4] = *(const float4*)&W2[(long)r * 64 + k4 * 4];
    }
    __syncthreads();

    c0 = make_float4(0.f, 0.f, 0.f, 0.f); c1 = c0; c2 = c0; c3 = c0;
#pragma unroll 8
    for (int k = 0; k < 64; k++) {
        float4 b = *(const float4*)&sB[k][tx * 4];
        float a0 = sA[ty * 4 + 0][k];
        float a1 = sA[ty * 4 + 1][k];
        float a2 = sA[ty * 4 + 2][k];
        float a3 = sA[ty * 4 + 3][k];
        c0.x += a0 * b.x; c0.y += a0 * b.y; c0.z += a0 * b.z; c0.w += a0 * b.w;
        c1.x += a1 * b.x; c1.y += a1 * b.y; c1.z += a1 * b.z; c1.w += a1 * b.w;
        c2.x += a2 * b.x; c2.y += a2 * b.y; c2.z += a2 * b.z; c2.w += a2 * b.w;
        c3.x += a3 * b.x; c3.y += a3 * b.y; c3.z += a3 * b.z; c3.w += a3 * b.w;
    }

    {
        float4 bb = *(const float4*)&B2[tx * 4];
        const int h16_off = layer * 64;     // layers 0/1 feed the next pull
#pragma unroll
        for (int rr = 0; rr < 4; rr++) {
            float4 c = (rr == 0) ? c0 : (rr == 1) ? c1 : (rr == 2) ? c2 : c3;
            int rg = tile + ty * 4 + rr;
            if (rg < NN) {
                float4 o;
                o.x = fmaxf(c.x + bb.x, 0.f); o.y = fmaxf(c.y + bb.y, 0.f);
                o.z = fmaxf(c.z + bb.z, 0.f); o.w = fmaxf(c.w + bb.w, 0.f);
                *(float4*)&g_hs[(long)rg * HS + out_off + tx * 4] = o;
                if (layer < 2) {
                    __half2 h0 = __floats2half2_rn(o.x, o.y);
                    __half2 h1 = __floats2half2_rn(o.z, o.w);
                    uint2 packed;
                    packed.x = *(unsigned*)&h0;
                    packed.y = *(unsigned*)&h1;
                    *(uint2*)&g_h16[(long)rg * 128 + h16_off + tx * 4] = packed;
                }
            }
        }
    }
}

// ---------------- graph segment bookkeeping (batch is sorted) --------------
__global__ void k_zero_cnt() {
    int i = blockIdx.x * 256 + threadIdx.x;
    if (i < NG) g_cnt[i] = 0;
}

__global__ void k_count(const void* __restrict__ batch) {
    int i = blockIdx.x * 256 + threadIdx.x;
    if (i < NN) atomicAdd(&g_cnt[(int)ld_idx(batch, i)], 1);
}

__global__ void __launch_bounds__(512) k_offsets() {
    __shared__ int s[NG];
    int t = threadIdx.x;
    s[t] = g_cnt[t];
    __syncthreads();
#pragma unroll
    for (int d = 1; d < NG; d <<= 1) {
        int u = (t >= d) ? s[t - d] : 0;
        __syncthreads();
        s[t] += u;
        __syncthreads();
    }
    g_off[t] = (t == 0) ? 0 : s[t - 1];
    if (t == NG - 1) g_off[NG] = s[t];
}

// ---------------- readout: mean/max/sum per graph + fc1 + fc2 + sigmoid ----
__global__ void __launch_bounds__(192) k_readout(const float* __restrict__ fc1w,
                                                 const float* __restrict__ fc1b,
                                                 const float* __restrict__ fc2w,
                                                 const float* __restrict__ fc2b,
                                                 float* __restrict__ out) {
    __shared__ float gv[GF];
    __shared__ float q[HH];

    int g = blockIdx.x;
    int f = threadIdx.x;
    int n0 = g_off[g], n1 = g_off[g + 1];

    float s = 0.f, m = -3.402823466e38f;
    for (int n = n0; n < n1; n++) {
        float v = g_hs[(long)n * HS + f];
        s += v;
        m = fmaxf(m, v);
    }
    int cnt = n1 - n0;
    gv[f]       = s / fmaxf((float)cnt, 1.f);
    gv[192 + f] = m;
    gv[384 + f] = s;
    __syncthreads();

    if (f < HH) {
        float a = fc1b[f];
#pragma unroll 4
        for (int k = 0; k < GF; k++) a += gv[k] * fc1w[k * 64 + f];
        q[f] = fmaxf(a, 0.f);
    }
    __syncthreads();

    if (f < 2) {
        float a = fc2b[f];
#pragma unroll
        for (int k = 0; k < HH; k++) a += q[k] * fc2w[k * 2 + f];
        out[g * 2 + f] = 1.f / (1.f + expf(-a));
    }
}

// ---------------- launch ----------------------------------------------------
extern "C" void kernel_launch(void* const* d_in, const int* in_sizes, int n_in,
                              void* d_out, int out_size) {
    const float* x     = (const float*)d_in[0];
    const void*  edge  = d_in[1];
    const void*  batch = d_in[2];
    const float* w1[3] = {(const float*)d_in[3],  (const float*)d_in[7],  (const float*)d_in[11]};
    const float* b1[3] = {(const float*)d_in[4],  (const float*)d_in[8],  (const float*)d_in[12]};
    const float* w2[3] = {(const float*)d_in[5],  (const float*)d_in[9],  (const float*)d_in[13]};
    const float* b2[3] = {(const float*)d_in[6],  (const float*)d_in[10], (const float*)d_in[14]};
    const float* eps   = (const float*)d_in[15];
    const float* fc1w  = (const float*)d_in[16];
    const float* fc1b  = (const float*)d_in[17];
    const float* fc2w  = (const float*)d_in[18];
    const float* fc2b  = (const float*)d_in[19];

    k_detect<<<1, 32>>>(edge);

    // fp16 copy of x for the L0 pull
    {
        long n4 = (long)NN * FIN / 4;
        k_cvt_x<<<(int)((n4 + 255) / 256), 256>>>(x);
    }

    // CSR build (once; reused by all 3 layers)
    k_zero_deg<<<(NN + 255) / 256, 256>>>();
    k_deg<<<(NE + 255) / 256, 256>>>(edge);
    k_bsum<<<NSB, 256>>>();
    k_bscan<<<1, 128>>>();
    k_rowptr<<<NSB, 256>>>();
    k_fill<<<(NE + 255) / 256, 256>>>(edge);

    const int pull_grid = (NN + 7) / 8;   // 8 warps per 256-thread block

    for (int L = 0; L < 3; L++) {
        const int fin  = (L == 0) ? FIN : HH;
        const int usex = (L == 0) ? 1 : 0;
        const int inoff = (L == 0) ? 0 : (L - 1) * 64;

        if (L == 0) {
            k_pull<FIN><<<pull_grid, 256>>>(1, 0);
        } else {
            k_pull<HH><<<pull_grid, 256>>>(0, inoff);
        }

        k_mlp<<<(NN + 63) / 64, 256>>>(x, usex, inoff, fin, eps, L,
                                       w1[L], b1[L], w2[L], b2[L], L * 64);
    }

    k_zero_cnt<<<2, 256>>>();
    k_count<<<(NN + 255) / 256, 256>>>(batch);
    k_offsets<<<1, NG>>>();
    k_readout<<<NG, 192>>>(fc1w, fc1b, fc2w, fc2b, (float*)d_out);
}

// round 6
// speedup vs baseline: 1.1210x; 1.1210x over previous
#include <cuda_runtime.h>
#include <math.h>

// Problem constants (fixed shapes)
#define NN 100000
#define NE 1600000
#define NG 512
#define FIN 128
#define HH 64
#define HS 192   // 3*H concat width
#define GF 576   // 3*HS graph feature width

#define SCAN_CH 1024
#define NSB ((NN + SCAN_CH - 1) / SCAN_CH)   // 98 scan blocks

// ---------------- scratch (static device globals; no runtime alloc) -------
__device__ __align__(16) float g_y[(size_t)NN * HH];      // 25.6 MB: projected feats
__device__ __align__(16) float g_agg[(size_t)NN * HH];    // 25.6 MB: pulled sums
__device__ __align__(16) float g_hs[(size_t)NN * HS];     // 76.8 MB: concat outputs
__device__ __align__(16) int g_rowptr[NN + 4];
__device__ __align__(16) int g_cursor[NN + 4];   // degree accumulator, then fill cursor
__device__ int g_csr[NE];
__device__ int g_bsum[NSB];
__device__ int g_boff[NSB + 1];
__device__ int g_cnt[NG];
__device__ int g_off[NG + 1];
__device__ int g_is64;

// ---------------- index dtype handling -------------------------------------
__device__ __forceinline__ long ld_idx(const void* p, long i) {
    if (g_is64) return (long)((const long long*)p)[i];
    return (long)((const int*)p)[i];
}

__global__ void k_detect(const void* edge) {
    // int64 indices < 2^31 => every odd 32-bit word is zero. Warp-parallel probe.
    const int* p = (const int*)edge;
    int t = threadIdx.x;
    int nz = (p[2 * t + 1] != 0) ? 1 : 0;
    unsigned m = __ballot_sync(0xffffffffu, nz);
    if (t == 0) g_is64 = (m == 0) ? 1 : 0;
}

// ---------------- CSR build (once per launch; reused by all 3 layers) ------
__global__ void k_zero_deg() {
    int i = blockIdx.x * 256 + threadIdx.x;
    if (i < NN) g_cursor[i] = 0;
}

__global__ void k_deg(const void* __restrict__ edge) {
    long e = (long)blockIdx.x * 256 + threadIdx.x;
    if (e < NE) {
        int d = (int)ld_idx(edge, (long)NE + e);
        atomicAdd(&g_cursor[d], 1);
    }
}

// Pass 1: per-block sums of 1024 degrees (256 threads x int4).
__global__ void __launch_bounds__(256) k_bsum() {
    __shared__ int ws[8];
    const int b = blockIdx.x, t = threadIdx.x;
    const int base = b * SCAN_CH + t * 4;
    int s = 0;
    if (base < NN) {
        int4 v = *(const int4*)&g_cursor[base];
        s = (v.x + v.y) + (v.z + v.w);
    }
#pragma unroll
    for (int o = 16; o > 0; o >>= 1) s += __shfl_down_sync(0xffffffffu, s, o);
    if ((t & 31) == 0) ws[t >> 5] = s;
    __syncthreads();
    if (t < 8) {
        int v = ws[t];
#pragma unroll
        for (int o = 4; o > 0; o >>= 1) v += __shfl_down_sync(0xffu, v, o);
        if (t == 0) g_bsum[b] = v;
    }
}

// Pass 2: scan the 98 block sums in one tiny block.
__global__ void __launch_bounds__(128) k_bscan() {
    __shared__ int s[128];
    int t = threadIdx.x;
    int v = (t < NSB) ? g_bsum[t] : 0;
    s[t] = v;
    __syncthreads();
#pragma unroll
    for (int d = 1; d < 128; d <<= 1) {
        int u = (t >= d) ? s[t - d] : 0;
        __syncthreads();
        s[t] += u;
        __syncthreads();
    }
    g_boff[t] = (t == 0) ? 0 : s[t - 1];
    if (t == NSB - 1) g_rowptr[NN] = s[t];
}

// Pass 3: per-block rescan -> rowptr, and initialize fill cursor in one pass.
__global__ void __launch_bounds__(256) k_rowptr() {
    __shared__ int s[256];
    const int b = blockIdx.x, t = threadIdx.x;
    const int base = b * SCAN_CH + t * 4;
    int d0 = 0, d1 = 0, d2 = 0, d3 = 0;
    if (base < NN) {
        int4 v = *(const int4*)&g_cursor[base];
        d0 = v.x; d1 = v.y; d2 = v.z; d3 = v.w;
    }
    s[t] = d0 + d1 + d2 + d3;
    __syncthreads();
#pragma unroll
    for (int d = 1; d < 256; d <<= 1) {
        int u = (t >= d) ? s[t - d] : 0;
        __syncthreads();
        s[t] += u;
        __syncthreads();
    }
    int off = g_boff[b] + ((t == 0) ? 0 : s[t - 1]);
    if (base < NN) {
        int4 r;
        r.x = off;
        r.y = off + d0;
        r.z = off + d0 + d1;
        r.w = off + d0 + d1 + d2;
        *(int4*)&g_rowptr[base] = r;
        *(int4*)&g_cursor[base] = r;   // cursor init fused
    }
}

__global__ void k_fill(const void* __restrict__ edge) {
    long e = (long)blockIdx.x * 256 + threadIdx.x;
    if (e < NE) {
        int s = (int)ld_idx(edge, e);
        int d = (int)ld_idx(edge, (long)NE + e);
        int pos = atomicAdd(&g_cursor[d], 1);
        g_csr[pos] = s;
    }
}

// ---------------- pull-aggregation over PROJECTED 64-wide rows --------------
// One warp per destination node; half-warps process neighbor pairs: lane =
// 16*h + c, half h gathers neighbor t+h's float4 chunk c. One warp-wide load
// instruction covers TWO neighbors (the latency/issue bound, halved).
__global__ void __launch_bounds__(256) k_pull64() {
    int warp = (blockIdx.x * 256 + threadIdx.x) >> 5;
    int lane = threadIdx.x & 31;
    if (warp >= NN) return;
    const int h = lane >> 4;
    const int c = lane & 15;
    int beg = g_rowptr[warp], end = g_rowptr[warp + 1];

    float4 acc = make_float4(0.f, 0.f, 0.f, 0.f);
    for (int j = beg; j < end; j += 32) {
        int n = min(32, end - j);
        int idx = (lane < n) ? g_csr[j + lane] : 0;
        int t = 0;
        for (; t + 8 <= n; t += 8) {          // 8 neighbors, 4 loads/lane in flight
            int u0 = __shfl_sync(0xffffffffu, idx, t + 0 + h);
            int u1 = __shfl_sync(0xffffffffu, idx, t + 2 + h);
            int u2 = __shfl_sync(0xffffffffu, idx, t + 4 + h);
            int u3 = __shfl_sync(0xffffffffu, idx, t + 6 + h);
            float4 v0 = *(const float4*)&g_y[(long)u0 * HH + c * 4];
            float4 v1 = *(const float4*)&g_y[(long)u1 * HH + c * 4];
            float4 v2 = *(const float4*)&g_y[(long)u2 * HH + c * 4];
            float4 v3 = *(const float4*)&g_y[(long)u3 * HH + c * 4];
            acc.x += (v0.x + v1.x) + (v2.x + v3.x);
            acc.y += (v0.y + v1.y) + (v2.y + v3.y);
            acc.z += (v0.z + v1.z) + (v2.z + v3.z);
            acc.w += (v0.w + v1.w) + (v2.w + v3.w);
        }
        for (; t < n; t += 2) {               // tail: 1-2 neighbors
            int tt = t + h;
            int sel = (tt < n) ? tt : t;
            int u = __shfl_sync(0xffffffffu, idx, sel);
            float4 v = *(const float4*)&g_y[(long)u * HH + c * 4];
            if (tt < n) {
                acc.x += v.x; acc.y += v.y; acc.z += v.z; acc.w += v.w;
            }
        }
    }
    // combine the two half-warp partials (same column c, different parity)
    acc.x += __shfl_xor_sync(0xffffffffu, acc.x, 16);
    acc.y += __shfl_xor_sync(0xffffffffu, acc.y, 16);
    acc.z += __shfl_xor_sync(0xffffffffu, acc.z, 16);
    acc.w += __shfl_xor_sync(0xffffffffu, acc.w, 16);
    if (h == 0) *(float4*)&g_agg[(long)warp * HH + c * 4] = acc;
}

// ---------------- GEMM1 (layer 0 only): y = x @ W1_0  ----------------------
// [100k x 128] @ [128 x 64], no bias/relu. 64x64 tile, 256 thr, 4x4 micro.
__global__ void __launch_bounds__(256) k_gemm1(const float* __restrict__ x,
                                               const float* __restrict__ W1) {
    __shared__ float sA[64][68];
    __shared__ float sB[64][68];

    const int tid = threadIdx.x;
    const int tx = tid & 15;
    const int ty = tid >> 4;
    const int tile = blockIdx.x * 64;

    float4 c0 = make_float4(0.f, 0.f, 0.f, 0.f), c1 = c0, c2 = c0, c3 = c0;

    for (int kc = 0; kc < FIN; kc += 64) {
#pragma unroll
        for (int s = 0; s < 4; s++) {
            int slot = tid + s * 256;
            int r  = slot >> 4;
            int k4 = slot & 15;
            int rg = tile + r;
            float4 v = make_float4(0.f, 0.f, 0.f, 0.f);
            if (rg < NN) v = *(const float4*)&x[(long)rg * FIN + kc + k4 * 4];
            *(float4*)&sA[r][k4 * 4] = v;
            *(float4*)&sB[r][k4 * 4] = *(const float4*)&W1[(long)(kc + r) * 64 + k4 * 4];
        }
        __syncthreads();
#pragma unroll 8
        for (int k = 0; k < 64; k++) {
            float4 b = *(const float4*)&sB[k][tx * 4];
            float a0 = sA[ty * 4 + 0][k];
            float a1 = sA[ty * 4 + 1][k];
            float a2 = sA[ty * 4 + 2][k];
            float a3 = sA[ty * 4 + 3][k];
            c0.x += a0 * b.x; c0.y += a0 * b.y; c0.z += a0 * b.z; c0.w += a0 * b.w;
            c1.x += a1 * b.x; c1.y += a1 * b.y; c1.z += a1 * b.z; c1.w += a1 * b.w;
            c2.x += a2 * b.x; c2.y += a2 * b.y; c2.z += a2 * b.z; c2.w += a2 * b.w;
            c3.x += a3 * b.x; c3.y += a3 * b.y; c3.z += a3 * b.z; c3.w += a3 * b.w;
        }
        __syncthreads();
    }

#pragma unroll
    for (int rr = 0; rr < 4; rr++) {
        float4 c = (rr == 0) ? c0 : (rr == 1) ? c1 : (rr == 2) ? c2 : c3;
        int rg = tile + ty * 4 + rr;
        if (rg < NN) *(float4*)&g_y[(long)rg * HH + tx * 4] = c;
    }
}

// ---------------- GEMM2: z = relu((1+eps)y + agg + b1); h = relu(z@W2+b2) ---
// Writes h into the g_hs concat slice; for layers 0/1 also computes
// y_next = h @ W1_next in-block (saves the h round-trip for projection).
__global__ void __launch_bounds__(256) k_gemm2(const float* __restrict__ eps, int layer,
                                               const float* __restrict__ B1,
                                               const float* __restrict__ W2,
                                               const float* __restrict__ B2,
                                               const float* __restrict__ W1n,
                                               int out_off, int has_next) {
    __shared__ float sA[64][68];
    __shared__ float sB[64][68];

    const int tid = threadIdx.x;
    const int tx = tid & 15;
    const int ty = tid >> 4;
    const int tile = blockIdx.x * 64;
    const float epsv = 1.0f + eps[layer];

    // Stage z = relu(epsv*y + agg + b1) and W2
#pragma unroll
    for (int s = 0; s < 4; s++) {
        int slot = tid + s * 256;
        int r  = slot >> 4;
        int k4 = slot & 15;
        int rg = tile + r;
        float4 v = make_float4(0.f, 0.f, 0.f, 0.f);
        if (rg < NN) {
            float4 yv = *(const float4*)&g_y[(long)rg * HH + k4 * 4];
            float4 av = *(const float4*)&g_agg[(long)rg * HH + k4 * 4];
            float4 bv = *(const float4*)&B1[k4 * 4];
            v.x = fmaxf(epsv * yv.x + av.x + bv.x, 0.f);
            v.y = fmaxf(epsv * yv.y + av.y + bv.y, 0.f);
            v.z = fmaxf(epsv * yv.z + av.z + bv.z, 0.f);
            v.w = fmaxf(epsv * yv.w + av.w + bv.w, 0.f);
        }
        *(float4*)&sA[r][k4 * 4] = v;
        *(float4*)&sB[r][k4 * 4] = *(const float4*)&W2[(long)r * 64 + k4 * 4];
    }
    __syncthreads();

    float4 c0 = make_float4(0.f, 0.f, 0.f, 0.f), c1 = c0, c2 = c0, c3 = c0;
#pragma unroll 8
    for (int k = 0; k < 64; k++) {
        float4 b = *(const float4*)&sB[k][tx * 4];
        float a0 = sA[ty * 4 + 0][k];
        float a1 = sA[ty * 4 + 1][k];
        float a2 = sA[ty * 4 + 2][k];
        float a3 = sA[ty * 4 + 3][k];
        c0.x += a0 * b.x; c0.y += a0 * b.y; c0.z += a0 * b.z; c0.w += a0 * b.w;
        c1.x += a1 * b.x; c1.y += a1 * b.y; c1.z += a1 * b.z; c1.w += a1 * b.w;
        c2.x += a2 * b.x; c2.y += a2 * b.y; c2.z += a2 * b.z; c2.w += a2 * b.w;
        c3.x += a3 * b.x; c3.y += a3 * b.y; c3.z += a3 * b.z; c3.w += a3 * b.w;
    }

    // h = relu(c + b2): store to g_hs, keep in registers for optional phase 2
    float4 bb = *(const float4*)&B2[tx * 4];
    float4 h0, h1, h2, h3;
    h0.x = fmaxf(c0.x + bb.x, 0.f); h0.y = fmaxf(c0.y + bb.y, 0.f);
    h0.z = fmaxf(c0.z + bb.z, 0.f); h0.w = fmaxf(c0.w + bb.w, 0.f);
    h1.x = fmaxf(c1.x + bb.x, 0.f); h1.y = fmaxf(c1.y + bb.y, 0.f);
    h1.z = fmaxf(c1.z + bb.z, 0.f); h1.w = fmaxf(c1.w + bb.w, 0.f);
    h2.x = fmaxf(c2.x + bb.x, 0.f); h2.y = fmaxf(c2.y + bb.y, 0.f);
    h2.z = fmaxf(c2.z + bb.z, 0.f); h2.w = fmaxf(c2.w + bb.w, 0.f);
    h3.x = fmaxf(c3.x + bb.x, 0.f); h3.y = fmaxf(c3.y + bb.y, 0.f);
    h3.z = fmaxf(c3.z + bb.z, 0.f); h3.w = fmaxf(c3.w + bb.w, 0.f);

    {
        int rg0 = tile + ty * 4;
        if (rg0 + 0 < NN) *(float4*)&g_hs[(long)(rg0 + 0) * HS + out_off + tx * 4] = h0;
        if (rg0 + 1 < NN) *(float4*)&g_hs[(long)(rg0 + 1) * HS + out_off + tx * 4] = h1;
        if (rg0 + 2 < NN) *(float4*)&g_hs[(long)(rg0 + 2) * HS + out_off + tx * 4] = h2;
        if (rg0 + 3 < NN) *(float4*)&g_hs[(long)(rg0 + 3) * HS + out_off + tx * 4] = h3;
    }

    if (!has_next) return;

    // Phase 2: y_next = h @ W1_next
    __syncthreads();                      // everyone done reading sA/sB
    *(float4*)&sA[ty * 4 + 0][tx * 4] = h0;
    *(float4*)&sA[ty * 4 + 1][tx * 4] = h1;
    *(float4*)&sA[ty * 4 + 2][tx * 4] = h2;
    *(float4*)&sA[ty * 4 + 3][tx * 4] = h3;
#pragma unroll
    for (int s = 0; s < 4; s++) {
        int slot = tid + s * 256;
        int r  = slot >> 4;
        int k4 = slot & 15;
        *(float4*)&sB[r][k4 * 4] = *(const float4*)&W1n[(long)r * 64 + k4 * 4];
    }
    __syncthreads();

    c0 = make_float4(0.f, 0.f, 0.f, 0.f); c1 = c0; c2 = c0; c3 = c0;
#pragma unroll 8
    for (int k = 0; k < 64; k++) {
        float4 b = *(const float4*)&sB[k][tx * 4];
        float a0 = sA[ty * 4 + 0][k];
        float a1 = sA[ty * 4 + 1][k];
        float a2 = sA[ty * 4 + 2][k];
        float a3 = sA[ty * 4 + 3][k];
        c0.x += a0 * b.x; c0.y += a0 * b.y; c0.z += a0 * b.z; c0.w += a0 * b.w;
        c1.x += a1 * b.x; c1.y += a1 * b.y; c1.z += a1 * b.z; c1.w += a1 * b.w;
        c2.x += a2 * b.x; c2.y += a2 * b.y; c2.z += a2 * b.z; c2.w += a2 * b.w;
        c3.x += a3 * b.x; c3.y += a3 * b.y; c3.z += a3 * b.z; c3.w += a3 * b.w;
    }

    {
        int rg0 = tile + ty * 4;
        if (rg0 + 0 < NN) *(float4*)&g_y[(long)(rg0 + 0) * HH + tx * 4] = c0;
        if (rg0 + 1 < NN) *(float4*)&g_y[(long)(rg0 + 1) * HH + tx * 4] = c1;
        if (rg0 + 2 < NN) *(float4*)&g_y[(long)(rg0 + 2) * HH + tx * 4] = c2;
        if (rg0 + 3 < NN) *(float4*)&g_y[(long)(rg0 + 3) * HH + tx * 4] = c3;
    }
}

// ---------------- graph segment bookkeeping (batch is sorted) --------------
__global__ void k_zero_cnt() {
    int i = blockIdx.x * 256 + threadIdx.x;
    if (i < NG) g_cnt[i] = 0;
}

__global__ void k_count(const void* __restrict__ batch) {
    int i = blockIdx.x * 256 + threadIdx.x;
    if (i < NN) atomicAdd(&g_cnt[(int)ld_idx(batch, i)], 1);
}

__global__ void __launch_bounds__(512) k_offsets() {
    __shared__ int s[NG];
    int t = threadIdx.x;
    s[t] = g_cnt[t];
    __syncthreads();
#pragma unroll
    for (int d = 1; d < NG; d <<= 1) {
        int u = (t >= d) ? s[t - d] : 0;
        __syncthreads();
        s[t] += u;
        __syncthreads();
    }
    g_off[t] = (t == 0) ? 0 : s[t - 1];
    if (t == NG - 1) g_off[NG] = s[t];
}

// ---------------- readout: mean/max/sum per graph + fc1 + fc2 + sigmoid ----
__global__ void __launch_bounds__(192) k_readout(const float* __restrict__ fc1w,
                                                 const float* __restrict__ fc1b,
                                                 const float* __restrict__ fc2w,
                                                 const float* __restrict__ fc2b,
                                                 float* __restrict__ out) {
    __shared__ float gv[GF];
    __shared__ float q[HH];

    int g = blockIdx.x;
    int f = threadIdx.x;
    int n0 = g_off[g], n1 = g_off[g + 1];

    float s = 0.f, m = -3.402823466e38f;
    for (int n = n0; n < n1; n++) {
        float v = g_hs[(long)n * HS + f];
        s += v;
        m = fmaxf(m, v);
    }
    int cnt = n1 - n0;
    gv[f]       = s / fmaxf((float)cnt, 1.f);
    gv[192 + f] = m;
    gv[384 + f] = s;
    __syncthreads();

    if (f < HH) {
        float a = fc1b[f];
#pragma unroll 4
        for (int k = 0; k < GF; k++) a += gv[k] * fc1w[k * 64 + f];
        q[f] = fmaxf(a, 0.f);
    }
    __syncthreads();

    if (f < 2) {
        float a = fc2b[f];
#pragma unroll
        for (int k = 0; k < HH; k++) a += q[k] * fc2w[k * 2 + f];
        out[g * 2 + f] = 1.f / (1.f + expf(-a));
    }
}

// ---------------- launch ----------------------------------------------------
extern "C" void kernel_launch(void* const* d_in, const int* in_sizes, int n_in,
                              void* d_out, int out_size) {
    const float* x     = (const float*)d_in[0];
    const void*  edge  = d_in[1];
    const void*  batch = d_in[2];
    const float* w1[3] = {(const float*)d_in[3],  (const float*)d_in[7],  (const float*)d_in[11]};
    const float* b1[3] = {(const float*)d_in[4],  (const float*)d_in[8],  (const float*)d_in[12]};
    const float* w2[3] = {(const float*)d_in[5],  (const float*)d_in[9],  (const float*)d_in[13]};
    const float* b2[3] = {(const float*)d_in[6],  (const float*)d_in[10], (const float*)d_in[14]};
    const float* eps   = (const float*)d_in[15];
    const float* fc1w  = (const float*)d_in[16];
    const float* fc1b  = (const float*)d_in[17];
    const float* fc2w  = (const float*)d_in[18];
    const float* fc2b  = (const float*)d_in[19];

    k_detect<<<1, 32>>>(edge);

    // CSR build (once; reused by all 3 layers)
    k_zero_deg<<<(NN + 255) / 256, 256>>>();
    k_deg<<<(NE + 255) / 256, 256>>>(edge);
    k_bsum<<<NSB, 256>>>();
    k_bscan<<<1, 128>>>();
    k_rowptr<<<NSB, 256>>>();
    k_fill<<<(NE + 255) / 256, 256>>>(edge);

    const int tile_grid = (NN + 63) / 64;
    const int pull_grid = (NN + 7) / 8;   // 8 warps per 256-thread block

    // Layer 0 projection: y0 = x @ W1_0
    k_gemm1<<<tile_grid, 256>>>(x, w1[0]);

    for (int L = 0; L < 3; L++) {
        k_pull64<<<pull_grid, 256>>>();
        const int has_next = (L < 2) ? 1 : 0;
        const float* w1n = has_next ? w1[L + 1] : w1[0];   // unused when !has_next
        k_gemm2<<<tile_grid, 256>>>(eps, L, b1[L], w2[L], b2[L], w1n,
                                    L * 64, has_next);
    }

    k_zero_cnt<<<2, 256>>>();
    k_count<<<(NN + 255) / 256, 256>>>(batch);
    k_offsets<<<1, NG>>>();
    k_readout<<<NG, 192>>>(fc1w, fc1b, fc2w, fc2b, (float*)d_out);
}

// round 7
// speedup vs baseline: 1.4877x; 1.3271x over previous
#include <cuda_runtime.h>
#include <cuda_fp16.h>
#include <mma.h>
#include <math.h>

using namespace nvcuda;

// Problem constants (fixed shapes)
#define NN 100000
#define NE 1600000
#define NG 512
#define FIN 128
#define HH 64
#define HS 192   // 3*H concat width
#define GF 576   // 3*HS graph feature width

#define SCAN_CH 1024
#define NSB ((NN + SCAN_CH - 1) / SCAN_CH)   // 98 scan blocks

// ---------------- scratch (static device globals; no runtime alloc) -------
// g_y padded by 64 rows: edge-tile wmma::store_matrix_sync may write past NN.
__device__ __align__(16) float g_y[(size_t)(NN + 64) * HH];
__device__ __align__(16) float g_agg[(size_t)NN * HH];
__device__ __align__(16) float g_hs[(size_t)NN * HS];
__device__ __align__(16) int g_rowptr[NN + 4];
__device__ __align__(16) int g_cursor[NN + 4];
__device__ int g_csr[NE];
__device__ int g_bsum[NSB];
__device__ int g_boff[NSB + 1];
__device__ int g_cnt[NG];
__device__ int g_off[NG + 1];
__device__ int g_is64;

// ---------------- index dtype handling -------------------------------------
__device__ __forceinline__ long ld_idx(const void* p, long i) {
    if (g_is64) return (long)((const long long*)p)[i];
    return (long)((const int*)p)[i];
}

__global__ void k_detect(const void* edge) {
    const int* p = (const int*)edge;
    int t = threadIdx.x;
    int nz = (p[2 * t + 1] != 0) ? 1 : 0;
    unsigned m = __ballot_sync(0xffffffffu, nz);
    if (t == 0) g_is64 = (m == 0) ? 1 : 0;
}

// ---------------- CSR build ------------------------------------------------
__global__ void k_zero_deg() {
    int i = blockIdx.x * 256 + threadIdx.x;
    if (i < NN) g_cursor[i] = 0;
}

__global__ void k_deg(const void* __restrict__ edge) {
    long e = (long)blockIdx.x * 256 + threadIdx.x;
    if (e < NE) {
        int d = (int)ld_idx(edge, (long)NE + e);
        atomicAdd(&g_cursor[d], 1);
    }
}

__global__ void __launch_bounds__(256) k_bsum() {
    __shared__ int ws[8];
    const int b = blockIdx.x, t = threadIdx.x;
    const int base = b * SCAN_CH + t * 4;
    int s = 0;
    if (base < NN) {
        int4 v = *(const int4*)&g_cursor[base];
        s = (v.x + v.y) + (v.z + v.w);
    }
#pragma unroll
    for (int o = 16; o > 0; o >>= 1) s += __shfl_down_sync(0xffffffffu, s, o);
    if ((t & 31) == 0) ws[t >> 5] = s;
    __syncthreads();
    if (t < 8) {
        int v = ws[t];
#pragma unroll
        for (int o = 4; o > 0; o >>= 1) v += __shfl_down_sync(0xffu, v, o);
        if (t == 0) g_bsum[b] = v;
    }
}

__global__ void __launch_bounds__(128) k_bscan() {
    __shared__ int s[128];
    int t = threadIdx.x;
    int v = (t < NSB) ? g_bsum[t] : 0;
    s[t] = v;
    __syncthreads();
#pragma unroll
    for (int d = 1; d < 128; d <<= 1) {
        int u = (t >= d) ? s[t - d] : 0;
        __syncthreads();
        s[t] += u;
        __syncthreads();
    }
    g_boff[t] = (t == 0) ? 0 : s[t - 1];
    if (t == NSB - 1) g_rowptr[NN] = s[t];
}

__global__ void __launch_bounds__(256) k_rowptr() {
    __shared__ int s[256];
    const int b = blockIdx.x, t = threadIdx.x;
    const int base = b * SCAN_CH + t * 4;
    int d0 = 0, d1 = 0, d2 = 0, d3 = 0;
    if (base < NN) {
        int4 v = *(const int4*)&g_cursor[base];
        d0 = v.x; d1 = v.y; d2 = v.z; d3 = v.w;
    }
    s[t] = d0 + d1 + d2 + d3;
    __syncthreads();
#pragma unroll
    for (int d = 1; d < 256; d <<= 1) {
        int u = (t >= d) ? s[t - d] : 0;
        __syncthreads();
        s[t] += u;
        __syncthreads();
    }
    int off = g_boff[b] + ((t == 0) ? 0 : s[t - 1]);
    if (base < NN) {
        int4 r;
        r.x = off;
        r.y = off + d0;
        r.z = off + d0 + d1;
        r.w = off + d0 + d1 + d2;
        *(int4*)&g_rowptr[base] = r;
        *(int4*)&g_cursor[base] = r;
    }
}

__global__ void k_fill(const void* __restrict__ edge) {
    long e = (long)blockIdx.x * 256 + threadIdx.x;
    if (e < NE) {
        int s = (int)ld_idx(edge, e);
        int d = (int)ld_idx(edge, (long)NE + e);
        int pos = atomicAdd(&g_cursor[d], 1);
        g_csr[pos] = s;
    }
}

// ---------------- pull-aggregation over PROJECTED 64-wide rows --------------
// One warp/node; half-warps pair up neighbors (one warp-load covers 2 edges).
__global__ void __launch_bounds__(256) k_pull64() {
    int warp = (blockIdx.x * 256 + threadIdx.x) >> 5;
    int lane = threadIdx.x & 31;
    if (warp >= NN) return;
    const int h = lane >> 4;
    const int c = lane & 15;
    int beg = g_rowptr[warp], end = g_rowptr[warp + 1];

    float4 acc = make_float4(0.f, 0.f, 0.f, 0.f);
    for (int j = beg; j < end; j += 32) {
        int n = min(32, end - j);
        int idx = (lane < n) ? g_csr[j + lane] : 0;
        int t = 0;
        for (; t + 8 <= n; t += 8) {
            int u0 = __shfl_sync(0xffffffffu, idx, t + 0 + h);
            int u1 = __shfl_sync(0xffffffffu, idx, t + 2 + h);
            int u2 = __shfl_sync(0xffffffffu, idx, t + 4 + h);
            int u3 = __shfl_sync(0xffffffffu, idx, t + 6 + h);
            float4 v0 = *(const float4*)&g_y[(long)u0 * HH + c * 4];
            float4 v1 = *(const float4*)&g_y[(long)u1 * HH + c * 4];
            float4 v2 = *(const float4*)&g_y[(long)u2 * HH + c * 4];
            float4 v3 = *(const float4*)&g_y[(long)u3 * HH + c * 4];
            acc.x += (v0.x + v1.x) + (v2.x + v3.x);
            acc.y += (v0.y + v1.y) + (v2.y + v3.y);
            acc.z += (v0.z + v1.z) + (v2.z + v3.z);
            acc.w += (v0.w + v1.w) + (v2.w + v3.w);
        }
        for (; t < n; t += 2) {
            int tt = t + h;
            int sel = (tt < n) ? tt : t;
            int u = __shfl_sync(0xffffffffu, idx, sel);
            float4 v = *(const float4*)&g_y[(long)u * HH + c * 4];
            if (tt < n) {
                acc.x += v.x; acc.y += v.y; acc.z += v.z; acc.w += v.w;
            }
        }
    }
    acc.x += __shfl_xor_sync(0xffffffffu, acc.x, 16);
    acc.y += __shfl_xor_sync(0xffffffffu, acc.y, 16);
    acc.z += __shfl_xor_sync(0xffffffffu, acc.z, 16);
    acc.w += __shfl_xor_sync(0xffffffffu, acc.w, 16);
    if (h == 0) *(float4*)&g_agg[(long)warp * HH + c * 4] = acc;
}

// ---------------- helpers ---------------------------------------------------
__device__ __forceinline__ void f4_to_h4(const float4& v, __half* dst) {
    __half2 h01 = __floats2half2_rn(v.x, v.y);
    __half2 h23 = __floats2half2_rn(v.z, v.w);
    uint2 u;
    u.x = *(unsigned*)&h01;
    u.y = *(unsigned*)&h23;
    *(uint2*)dst = u;
}

// ---------------- GEMM1 (layer 0 only): y = x @ W1_0, tensor cores ---------
// [64 x 128] @ [128 x 64] per block. 8 warps, each 16x32 output tile.
__global__ void __launch_bounds__(256) k_gemm1(const float* __restrict__ x,
                                               const float* __restrict__ W1) {
    __shared__ __align__(16) __half sA[64][136];   // 64x128 (+8 pad)
    __shared__ __align__(16) __half sB[128][72];   // 128x64 (+8 pad)

    const int tid = threadIdx.x;
    const int wid = tid >> 5;
    const int tile = blockIdx.x * 64;

    // Stage x tile (fp32 -> fp16) and W1
#pragma unroll
    for (int s = 0; s < 8; s++) {
        int slot = tid + s * 256;               // 0..2047
        int row = slot >> 5;                    // /32 float4 per row
        int c4  = slot & 31;
        int rg = tile + row;
        float4 v = make_float4(0.f, 0.f, 0.f, 0.f);
        if (rg < NN) v = *(const float4*)&x[(long)rg * FIN + c4 * 4];
        f4_to_h4(v, &sA[row][c4 * 4]);

        int wr = slot >> 4;                     // 0..127
        int wc4 = slot & 15;
        float4 w = *(const float4*)&W1[(long)wr * 64 + wc4 * 4];
        f4_to_h4(w, &sB[wr][wc4 * 4]);
    }
    __syncthreads();

    const int row0 = (wid >> 1) * 16;
    const int col0 = (wid & 1) * 32;

    wmma::fragment<wmma::accumulator, 16, 16, 16, float> c0, c1;
    wmma::fill_fragment(c0, 0.f);
    wmma::fill_fragment(c1, 0.f);
#pragma unroll
    for (int k = 0; k < 8; k++) {
        wmma::fragment<wmma::matrix_a, 16, 16, 16, __half, wmma::row_major> a;
        wmma::fragment<wmma::matrix_b, 16, 16, 16, __half, wmma::row_major> b0, b1;
        wmma::load_matrix_sync(a, &sA[row0][k * 16], 136);
        wmma::load_matrix_sync(b0, &sB[k * 16][col0], 72);
        wmma::load_matrix_sync(b1, &sB[k * 16][col0 + 16], 72);
        wmma::mma_sync(c0, a, b0, c0);
        wmma::mma_sync(c1, a, b1, c1);
    }
    // g_y is padded; direct global store is safe even for the edge tile.
    wmma::store_matrix_sync(&g_y[(long)(tile + row0) * HH + col0], c0, HH, wmma::mem_row_major);
    wmma::store_matrix_sync(&g_y[(long)(tile + row0) * HH + col0 + 16], c1, HH, wmma::mem_row_major);
}

// ---------------- GEMM2: z = relu((1+eps)y+agg+b1); h = relu(z@W2+b2) -------
// Tensor-core version; optional phase2 computes y_next = h @ W1_next.
__global__ void __launch_bounds__(256) k_gemm2(const float* __restrict__ eps, int layer,
                                               const float* __restrict__ B1,
                                               const float* __restrict__ W2,
                                               const float* __restrict__ B2,
                                               const float* __restrict__ W1n,
                                               int out_off, int has_next) {
    __shared__ __align__(16) __half sA[64][72];
    __shared__ __align__(16) __half sB[64][72];
    __shared__ __align__(16) float  sC[64][72];

    const int tid = threadIdx.x;
    const int wid = tid >> 5;
    const int tile = blockIdx.x * 64;
    const float epsv = 1.0f + eps[layer];

    // Stage z (fp32 computed, fp16 stored) and W2
#pragma unroll
    for (int s = 0; s < 4; s++) {
        int slot = tid + s * 256;               // 0..1023
        int row = slot >> 4;
        int c4  = slot & 15;
        int rg = tile + row;
        float4 v = make_float4(0.f, 0.f, 0.f, 0.f);
        if (rg < NN) {
            float4 yv = *(const float4*)&g_y[(long)rg * HH + c4 * 4];
            float4 av = *(const float4*)&g_agg[(long)rg * HH + c4 * 4];
            float4 bv = *(const float4*)&B1[c4 * 4];
            v.x = fmaxf(epsv * yv.x + av.x + bv.x, 0.f);
            v.y = fmaxf(epsv * yv.y + av.y + bv.y, 0.f);
            v.z = fmaxf(epsv * yv.z + av.z + bv.z, 0.f);
            v.w = fmaxf(epsv * yv.w + av.w + bv.w, 0.f);
        }
        f4_to_h4(v, &sA[row][c4 * 4]);
        float4 w = *(const float4*)&W2[(long)row * 64 + c4 * 4];
        f4_to_h4(w, &sB[row][c4 * 4]);
    }
    __syncthreads();

    const int row0 = (wid >> 1) * 16;
    const int col0 = (wid & 1) * 32;

    wmma::fragment<wmma::accumulator, 16, 16, 16, float> c0, c1;
    wmma::fill_fragment(c0, 0.f);
    wmma::fill_fragment(c1, 0.f);
#pragma unroll
    for (int k = 0; k < 4; k++) {
        wmma::fragment<wmma::matrix_a, 16, 16, 16, __half, wmma::row_major> a;
        wmma::fragment<wmma::matrix_b, 16, 16, 16, __half, wmma::row_major> b0, b1;
        wmma::load_matrix_sync(a, &sA[row0][k * 16], 72);
        wmma::load_matrix_sync(b0, &sB[k * 16][col0], 72);
        wmma::load_matrix_sync(b1, &sB[k * 16][col0 + 16], 72);
        wmma::mma_sync(c0, a, b0, c0);
        wmma::mma_sync(c1, a, b1, c1);
    }
    wmma::store_matrix_sync(&sC[row0][col0], c0, 72, wmma::mem_row_major);
    wmma::store_matrix_sync(&sC[row0][col0 + 16], c1, 72, wmma::mem_row_major);
    __syncthreads();   // all mma done (sA/sB free), sC complete

    // Epilogue: h = relu(sC + b2) -> g_hs (fp32) and sA (fp16, for phase2)
#pragma unroll
    for (int s = 0; s < 4; s++) {
        int slot = tid + s * 256;
        int row = slot >> 4;
        int c4  = slot & 15;
        int rg = tile + row;
        float4 v = *(const float4*)&sC[row][c4 * 4];
        float4 bv = *(const float4*)&B2[c4 * 4];
        v.x = fmaxf(v.x + bv.x, 0.f);
        v.y = fmaxf(v.y + bv.y, 0.f);
        v.z = fmaxf(v.z + bv.z, 0.f);
        v.w = fmaxf(v.w + bv.w, 0.f);
        if (rg < NN) *(float4*)&g_hs[(long)rg * HS + out_off + c4 * 4] = v;
        f4_to_h4(v, &sA[row][c4 * 4]);
        if (has_next) {
            float4 w = *(const float4*)&W1n[(long)row * 64 + c4 * 4];
            f4_to_h4(w, &sB[row][c4 * 4]);
        }
    }
    if (!has_next) return;
    __syncthreads();

    // Phase 2: y_next = h @ W1_next
    wmma::fill_fragment(c0, 0.f);
    wmma::fill_fragment(c1, 0.f);
#pragma unroll
    for (int k = 0; k < 4; k++) {
        wmma::fragment<wmma::matrix_a, 16, 16, 16, __half, wmma::row_major> a;
        wmma::fragment<wmma::matrix_b, 16, 16, 16, __half, wmma::row_major> b0, b1;
        wmma::load_matrix_sync(a, &sA[row0][k * 16], 72);
        wmma::load_matrix_sync(b0, &sB[k * 16][col0], 72);
        wmma::load_matrix_sync(b1, &sB[k * 16][col0 + 16], 72);
        wmma::mma_sync(c0, a, b0, c0);
        wmma::mma_sync(c1, a, b1, c1);
    }
    wmma::store_matrix_sync(&g_y[(long)(tile + row0) * HH + col0], c0, HH, wmma::mem_row_major);
    wmma::store_matrix_sync(&g_y[(long)(tile + row0) * HH + col0 + 16], c1, HH, wmma::mem_row_major);
}

// ---------------- graph segment bookkeeping (batch is sorted) --------------
__global__ void k_zero_cnt() {
    int i = blockIdx.x * 256 + threadIdx.x;
    if (i < NG) g_cnt[i] = 0;
}

__global__ void k_count(const void* __restrict__ batch) {
    int i = blockIdx.x * 256 + threadIdx.x;
    if (i < NN) atomicAdd(&g_cnt[(int)ld_idx(batch, i)], 1);
}

__global__ void __launch_bounds__(512) k_offsets() {
    __shared__ int s[NG];
    int t = threadIdx.x;
    s[t] = g_cnt[t];
    __syncthreads();
#pragma unroll
    for (int d = 1; d < NG; d <<= 1) {
        int u = (t >= d) ? s[t - d] : 0;
        __syncthreads();
        s[t] += u;
        __syncthreads();
    }
    g_off[t] = (t == 0) ? 0 : s[t - 1];
    if (t == NG - 1) g_off[NG] = s[t];
}

// ---------------- readout: mean/max/sum per graph + fc1 + fc2 + sigmoid ----
__global__ void __launch_bounds__(192) k_readout(const float* __restrict__ fc1w,
                                                 const float* __restrict__ fc1b,
                                                 const float* __restrict__ fc2w,
                                                 const float* __restrict__ fc2b,
                                                 float* __restrict__ out) {
    __shared__ float gv[GF];
    __shared__ float q[HH];

    int g = blockIdx.x;
    int f = threadIdx.x;
    int n0 = g_off[g], n1 = g_off[g + 1];

    float s = 0.f, m = -3.402823466e38f;
    for (int n = n0; n < n1; n++) {
        float v = g_hs[(long)n * HS + f];
        s += v;
        m = fmaxf(m, v);
    }
    int cnt = n1 - n0;
    gv[f]       = s / fmaxf((float)cnt, 1.f);
    gv[192 + f] = m;
    gv[384 + f] = s;
    __syncthreads();

    if (f < HH) {
        float a = fc1b[f];
#pragma unroll 4
        for (int k = 0; k < GF; k++) a += gv[k] * fc1w[k * 64 + f];
        q[f] = fmaxf(a, 0.f);
    }
    __syncthreads();

    if (f < 2) {
        float a = fc2b[f];
#pragma unroll
        for (int k = 0; k < HH; k++) a += q[k] * fc2w[k * 2 + f];
        out[g * 2 + f] = 1.f / (1.f + expf(-a));
    }
}

// ---------------- launch ----------------------------------------------------
extern "C" void kernel_launch(void* const* d_in, const int* in_sizes, int n_in,
                              void* d_out, int out_size) {
    const float* x     = (const float*)d_in[0];
    const void*  edge  = d_in[1];
    const void*  batch = d_in[2];
    const float* w1[3] = {(const float*)d_in[3],  (const float*)d_in[7],  (const float*)d_in[11]};
    const float* b1[3] = {(const float*)d_in[4],  (const float*)d_in[8],  (const float*)d_in[12]};
    const float* w2[3] = {(const float*)d_in[5],  (const float*)d_in[9],  (const float*)d_in[13]};
    const float* b2[3] = {(const float*)d_in[6],  (const float*)d_in[10], (const float*)d_in[14]};
    const float* eps   = (const float*)d_in[15];
    const float* fc1w  = (const float*)d_in[16];
    const float* fc1b  = (const float*)d_in[17];
    const float* fc2w  = (const float*)d_in[18];
    const float* fc2b  = (const float*)d_in[19];

    k_detect<<<1, 32>>>(edge);

    // CSR build (once; reused by all 3 layers)
    k_zero_deg<<<(NN + 255) / 256, 256>>>();
    k_deg<<<(NE + 255) / 256, 256>>>(edge);
    k_bsum<<<NSB, 256>>>();
    k_bscan<<<1, 128>>>();
    k_rowptr<<<NSB, 256>>>();
    k_fill<<<(NE + 255) / 256, 256>>>(edge);

    const int tile_grid = (NN + 63) / 64;
    const int pull_grid = (NN + 7) / 8;

    // Layer 0 projection: y0 = x @ W1_0
    k_gemm1<<<tile_grid, 256>>>(x, w1[0]);

    for (int L = 0; L < 3; L++) {
        k_pull64<<<pull_grid, 256>>>();
        const int has_next = (L < 2) ? 1 : 0;
        const float* w1n = has_next ? w1[L + 1] : w1[0];
        k_gemm2<<<tile_grid, 256>>>(eps, L, b1[L], w2[L], b2[L], w1n,
                                    L * 64, has_next);
    }

    k_zero_cnt<<<2, 256>>>();
    k_count<<<(NN + 255) / 256, 256>>>(batch);
    k_offsets<<<1, NG>>>();
    k_readout<<<NG, 192>>>(fc1w, fc1b, fc2w, fc2b, (float*)d_out);
}